// round 17
// baseline (speedup 1.0000x reference)
#include <cuda_runtime.h>
#include <cuda_fp16.h>

#define B_    64
#define S_    512
#define H_    128
#define NH_   4
#define NHH_  512
#define QSCALE 0.08838834764831845f   /* 1/sqrt(128) */
#define LOG2E_ 1.4426950408889634f
#define NEG_INF_ -1e9f
#define P_    272                      /* smem row pitch in bytes (136 halves) */

// ---------------- row-major fp16 tensors -------------------------------------
__device__ __half g_Qh [(size_t)B_ * NH_ * S_ * H_];   // [bh][s][d], Q scaled by QSCALE*log2e
__device__ __half g_Kh [(size_t)B_ * NH_ * S_ * H_];   // [bh][s][d]
__device__ __half g_Vh [(size_t)B_ * NH_ * S_ * H_];   // [bh][s][d]  (row-major! ldmatrix.trans in PV)
__device__ __half g_ctxh[(size_t)B_ * S_ * NHH_];      // [tok][nhh]
__device__ __half g_Wh [3 * 512 * 128];                // [mat][n][k], Wq*QSCALE*log2e folded
__device__ __half g_Woh[128 * 512];                    // [n][k]

// ---------------- helpers ----------------------------------------------------
__device__ __forceinline__ unsigned h2u(float x, float y) {
    __half2 h = __floats2half2_rn(x, y);
    return *reinterpret_cast<unsigned*>(&h);
}
__device__ __forceinline__ unsigned fu(float x) { return __float_as_uint(x); }
__device__ __forceinline__ float    uf(unsigned u) { return __uint_as_float(u); }

__device__ __forceinline__ unsigned ex2h2(float x, float y) {
    __half2 h = __floats2half2_rn(x, y);
    unsigned u = *reinterpret_cast<unsigned*>(&h);
    asm("ex2.approx.f16x2 %0, %0;" : "+r"(u));
    return u;
}
__device__ __forceinline__ float2 uh2f2(unsigned u) {
    __half2 h = *reinterpret_cast<__half2*>(&u);
    return __half22float2(h);
}

__device__ __forceinline__ void mma_f16(float c[4],
                                        unsigned a0, unsigned a1, unsigned a2, unsigned a3,
                                        unsigned b0, unsigned b1) {
    asm volatile(
        "mma.sync.aligned.m16n8k16.row.col.f32.f16.f16.f32 "
        "{%0,%1,%2,%3}, {%4,%5,%6,%7}, {%8,%9}, {%0,%1,%2,%3};"
        : "+f"(c[0]), "+f"(c[1]), "+f"(c[2]), "+f"(c[3])
        : "r"(a0), "r"(a1), "r"(a2), "r"(a3), "r"(b0), "r"(b1));
}

__device__ __forceinline__ void ldsm4(unsigned& r0, unsigned& r1, unsigned& r2, unsigned& r3,
                                      unsigned a) {
    asm volatile("ldmatrix.sync.aligned.m8n8.x4.shared.b16 {%0,%1,%2,%3}, [%4];"
                 : "=r"(r0), "=r"(r1), "=r"(r2), "=r"(r3) : "r"(a));
}
__device__ __forceinline__ void ldsm4t(unsigned& r0, unsigned& r1, unsigned& r2, unsigned& r3,
                                       unsigned a) {
    asm volatile("ldmatrix.sync.aligned.m8n8.x4.trans.shared.b16 {%0,%1,%2,%3}, [%4];"
                 : "=r"(r0), "=r"(r1), "=r"(r2), "=r"(r3) : "r"(a));
}

__device__ __forceinline__ void cpa16(void* dst, const void* src) {
    unsigned d = (unsigned)__cvta_generic_to_shared(dst);
    asm volatile("cp.async.cg.shared.global [%0], [%1], 16;" :: "r"(d), "l"(src));
}
__device__ __forceinline__ void cp_commit() { asm volatile("cp.async.commit_group;"); }
template<int N> __device__ __forceinline__ void cp_wait() {
    asm volatile("cp.async.wait_group %0;" :: "n"(N));
}

// =============================================================================
// Kernel 0: pack weights to row-major fp16 [n][k]. 1024 blocks x 256.
// Wq gets QSCALE*LOG2E folded (scores emerge in log2 domain).
// =============================================================================
__global__ void __launch_bounds__(256) prep_kernel(
    const float* __restrict__ Wq, const float* __restrict__ Wk,
    const float* __restrict__ Wv, const float* __restrict__ Wo)
{
    int idx = blockIdx.x * 256 + threadIdx.x;
    if (idx < 3 * 512 * 128) {
        int n = idx & 511, k = (idx >> 9) & 127, mat = idx >> 16;
        const float* W = (mat == 0) ? Wq : (mat == 1) ? Wk : Wv;
        float scl = (mat == 0) ? QSCALE * LOG2E_ : 1.0f;
        g_Wh[(size_t)mat * 65536 + (size_t)n * 128 + k] =
            __float2half_rn(W[(size_t)k * NHH_ + n] * scl);
    } else {
        int i2 = idx - 3 * 512 * 128;         // 128*512
        int n = i2 & 127, k = i2 >> 7;
        g_Woh[(size_t)n * 512 + k] = __float2half_rn(Wo[(size_t)k * H_ + n]);
    }
}

// =============================================================================
// Kernel 1: QKV projection, m-resident, fp16 MMA via ldmatrix fragments.
// CTA = 64 tokens; 12 (mat,hq) chunks of n=128, k=128; 8 warps (2m x 4n).
// smem 87040 B: As 64xP_ @0, Ws0 @17408, Ws1 @52224.
// V epilogue = plain row-major store (no transpose — PV uses ldmatrix.trans).
// =============================================================================
__global__ void __launch_bounds__(256, 2) qkv_kernel(const float* __restrict__ enc)
{
    extern __shared__ char smc[];
    const unsigned sb = (unsigned)__cvta_generic_to_shared(smc);
    const int tid = threadIdx.x, lane = tid & 31, wid = tid >> 5;
    const int gid = lane >> 2, tig = lane & 3;
    const int mw = wid & 1, nw = wid >> 1;
    const int m0 = blockIdx.x * 64;

    // ---- enc tile to fp16, row-major, pitch P_ ----
#pragma unroll
    for (int t = 0; t < 8; t++) {
        int idx = tid + t * 256;
        int r = idx >> 5, sl = idx & 31;
        float4 a = *(const float4*)&enc[(size_t)(m0 + r) * H_ + sl * 4];
        float2 st;
        st.x = uf(h2u(a.x, a.y));
        st.y = uf(h2u(a.z, a.w));
        *(float2*)(smc + r * P_ + 8 * sl) = st;
    }

    // prefetch W chunk 0 into Ws0
#pragma unroll
    for (int t = 0; t < 8; t++) {
        int idx = tid + t * 256;
        int r = idx >> 4, q = idx & 15;
        cpa16(smc + 17408 + r * P_ + 16 * q, g_Wh + (size_t)r * 128 + 8 * q);
    }
    cp_commit();

    const unsigned aA = sb + (mw * 32 + (lane & 15)) * P_ + ((lane & 16) ? 16 : 0);
    const unsigned aBl = (nw * 32 + (lane & 7) + ((lane & 16) >> 1)) * P_ + ((lane & 8) ? 16 : 0);

    for (int ch = 0; ch < 12; ch++) {
        const int mat = ch >> 2, hq = ch & 3;

        __syncthreads();                 // prev MMA done with the prefetch target
        if (ch < 11) {
            const int nm = (ch + 1) >> 2, nh = (ch + 1) & 3;
            char* wn = smc + 17408 + (((ch + 1) & 1) ? 34816 : 0);
            const __half* src = g_Wh + (size_t)(nm * 512 + nh * 128) * 128;
#pragma unroll
            for (int t = 0; t < 8; t++) {
                int idx = tid + t * 256;
                int r = idx >> 4, q = idx & 15;
                cpa16(wn + r * P_ + 16 * q, src + (size_t)r * 128 + 8 * q);
            }
            cp_commit();
            cp_wait<1>();
        } else {
            cp_wait<0>();
        }
        __syncthreads();                 // W(ch) + As visible

        const unsigned aB = sb + 17408 + ((ch & 1) ? 34816u : 0u) + aBl;
        float c[2][4][4];
#pragma unroll
        for (int mt = 0; mt < 2; mt++)
#pragma unroll
            for (int nt = 0; nt < 4; nt++)
#pragma unroll
                for (int j = 0; j < 4; j++) c[mt][nt][j] = 0.0f;

#pragma unroll
        for (int ks = 0; ks < 8; ks++) {
            unsigned a00, a01, a02, a03, a10, a11, a12, a13;
            ldsm4(a00, a01, a02, a03, aA + ks * 32);
            ldsm4(a10, a11, a12, a13, aA + 16 * P_ + ks * 32);
#pragma unroll
            for (int nt2 = 0; nt2 < 2; nt2++) {
                unsigned b0, b1, b2, b3;
                ldsm4(b0, b1, b2, b3, aB + nt2 * 16 * P_ + ks * 32);
                mma_f16(c[0][2 * nt2],     a00, a01, a02, a03, b0, b1);
                mma_f16(c[0][2 * nt2 + 1], a00, a01, a02, a03, b2, b3);
                mma_f16(c[1][2 * nt2],     a10, a11, a12, a13, b0, b1);
                mma_f16(c[1][2 * nt2 + 1], a10, a11, a12, a13, b2, b3);
            }
        }

        // ---- epilogue: row-major fp16 stores (Q/K/V identical) ----
        __half* dst = (mat == 0) ? g_Qh : (mat == 1) ? g_Kh : g_Vh;
#pragma unroll
        for (int mt = 0; mt < 2; mt++) {
            int rr = mw * 32 + mt * 16 + gid;
            int tok = m0 + rr, bbv = tok >> 9, srow = tok & 511;
            size_t b0a = ((size_t)((bbv * NH_ + hq) * S_ + srow)) * H_;
            size_t b1a = b0a + 8 * H_;
#pragma unroll
            for (int nt = 0; nt < 4; nt++) {
                int n = nw * 32 + 8 * nt + 2 * tig;
                *(unsigned*)&dst[b0a + n] = h2u(c[mt][nt][0], c[mt][nt][1]);
                *(unsigned*)&dst[b1a + n] = h2u(c[mt][nt][2], c[mt][nt][3]);
            }
        }
    }
}

// =============================================================================
// Kernel 2: FA2 flash attention, K-TILE 64, 2 CTAs/SM, ldmatrix fragments,
// fp16x2 exp2 softmax.  Q-tile 128, 8 warps x 16 q-rows x 64 k.
// smem 104448 B: Qh @0 (128xP_), Kb @34816 (2x 64xP_), Vb @69632 (2x 64xP_).
// =============================================================================
__global__ void __launch_bounds__(256, 2) attn_kernel(const int* __restrict__ mask)
{
    extern __shared__ char smc[];
    const unsigned sb = (unsigned)__cvta_generic_to_shared(smc);
    const int tid = threadIdx.x, lane = tid & 31, wq = tid >> 5;
    const int gid = lane >> 2, tig = lane & 3;
    const int q0 = blockIdx.x * 128;
    const int hq = blockIdx.y, bb = blockIdx.z;
    const int bh = bb * NH_ + hq;
    const int r0 = wq * 16 + gid;
    const int gq0 = q0 + r0, gq1 = gq0 + 8;

    // prefetch Q + K tile 0 + V tile 0
#pragma unroll
    for (int t = 0; t < 8; t++) {
        int idx = tid + t * 256;
        int r = idx >> 4, q = idx & 15;
        cpa16(smc + r * P_ + 16 * q, g_Qh + ((size_t)bh * S_ + q0 + r) * H_ + 8 * q);
    }
#pragma unroll
    for (int t = 0; t < 4; t++) {
        int idx = tid + t * 256;
        int r = idx >> 4, q = idx & 15;
        cpa16(smc + 34816 + r * P_ + 16 * q, g_Kh + ((size_t)bh * S_ + r) * H_ + 8 * q);
    }
#pragma unroll
    for (int t = 0; t < 4; t++) {
        int idx = tid + t * 256;
        int r = idx >> 4, q = idx & 15;
        cpa16(smc + 69632 + r * P_ + 16 * q, g_Vh + ((size_t)bh * S_ + r) * H_ + 8 * q);
    }
    cp_commit();

    const unsigned aQ  = sb + (wq * 16 + (lane & 15)) * P_ + ((lane & 16) ? 16 : 0);
    const unsigned aKb = sb + 34816 + ((lane & 7) + ((lane & 16) >> 1)) * P_ + ((lane & 8) ? 16 : 0);
    const unsigned aVb = sb + 69632 + (lane & 15) * P_ + ((lane & 16) ? 16 : 0);

    float O[16][4];
#pragma unroll
    for (int nt = 0; nt < 16; nt++)
#pragma unroll
        for (int j = 0; j < 4; j++) O[nt][j] = 0.0f;
    float m0v = -1e30f, m1v = -1e30f, l0 = 0.0f, l1 = 0.0f;

    for (int kt = 0; kt < 8; kt++) {
        const int k0 = kt * 64;

        __syncthreads();                 // all warps done reading the prefetch targets
        if (kt < 7) {
            const int kn0 = k0 + 64;
            char* kn = smc + 34816 + (((kt + 1) & 1) ? 17408 : 0);
            char* vn = smc + 69632 + (((kt + 1) & 1) ? 17408 : 0);
#pragma unroll
            for (int t = 0; t < 4; t++) {
                int idx = tid + t * 256;
                int r = idx >> 4, q = idx & 15;
                cpa16(kn + r * P_ + 16 * q, g_Kh + ((size_t)bh * S_ + kn0 + r) * H_ + 8 * q);
            }
#pragma unroll
            for (int t = 0; t < 4; t++) {
                int idx = tid + t * 256;
                int r = idx >> 4, q = idx & 15;
                cpa16(vn + r * P_ + 16 * q, g_Vh + ((size_t)bh * S_ + kn0 + r) * H_ + 8 * q);
            }
            cp_commit();
            cp_wait<1>();                // tile kt complete
        } else {
            cp_wait<0>();
        }
        __syncthreads();                 // tile kt visible

        // ---- S = Q K^T ----
        const unsigned kb = aKb + ((kt & 1) ? 17408u : 0u);
        float c[8][4];
#pragma unroll
        for (int nt = 0; nt < 8; nt++)
#pragma unroll
            for (int j = 0; j < 4; j++) c[nt][j] = 0.0f;
#pragma unroll
        for (int ks = 0; ks < 8; ks++) {
            unsigned a0, a1, a2, a3;
            ldsm4(a0, a1, a2, a3, aQ + ks * 32);
#pragma unroll
            for (int nt2 = 0; nt2 < 4; nt2++) {
                unsigned b0, b1, b2, b3;
                ldsm4(b0, b1, b2, b3, kb + nt2 * 16 * P_ + ks * 32);
                mma_f16(c[2 * nt2],     a0, a1, a2, a3, b0, b1);
                mma_f16(c[2 * nt2 + 1], a0, a1, a2, a3, b2, b3);
            }
        }

        // ---- mask + row max (warp-local) ----
        float mx0 = -1e30f, mx1 = -1e30f;
#pragma unroll
        for (int nt = 0; nt < 8; nt++) {
            int kc = k0 + 8 * nt + 2 * tig;
            int2 mk0 = *(const int2*)&mask[((size_t)bb * S_ + gq0) * S_ + kc];
            int2 mk1 = *(const int2*)&mask[((size_t)bb * S_ + gq1) * S_ + kc];
            if (mk0.x == 0) c[nt][0] = NEG_INF_;
            if (mk0.y == 0) c[nt][1] = NEG_INF_;
            if (mk1.x == 0) c[nt][2] = NEG_INF_;
            if (mk1.y == 0) c[nt][3] = NEG_INF_;
            mx0 = fmaxf(mx0, fmaxf(c[nt][0], c[nt][1]));
            mx1 = fmaxf(mx1, fmaxf(c[nt][2], c[nt][3]));
        }
        mx0 = fmaxf(mx0, __shfl_xor_sync(0xffffffffu, mx0, 1));
        mx0 = fmaxf(mx0, __shfl_xor_sync(0xffffffffu, mx0, 2));
        mx1 = fmaxf(mx1, __shfl_xor_sync(0xffffffffu, mx1, 1));
        mx1 = fmaxf(mx1, __shfl_xor_sync(0xffffffffu, mx1, 2));

        float nm0 = fmaxf(m0v, mx0), nm1 = fmaxf(m1v, mx1);
        float al0 = exp2f(m0v - nm0), al1 = exp2f(m1v - nm1);
        m0v = nm0; m1v = nm1;

        // ---- exponentials in fp16x2 (outputs ARE the PV a-frags) ----
        unsigned pe[8][2];
        float s0 = 0.0f, s1 = 0.0f;
#pragma unroll
        for (int nt = 0; nt < 8; nt++) {
            pe[nt][0] = ex2h2(c[nt][0] - nm0, c[nt][1] - nm0);
            pe[nt][1] = ex2h2(c[nt][2] - nm1, c[nt][3] - nm1);
            float2 f0 = uh2f2(pe[nt][0]);
            float2 f1 = uh2f2(pe[nt][1]);
            s0 += f0.x + f0.y;
            s1 += f1.x + f1.y;
        }
        s0 += __shfl_xor_sync(0xffffffffu, s0, 1);
        s0 += __shfl_xor_sync(0xffffffffu, s0, 2);
        s1 += __shfl_xor_sync(0xffffffffu, s1, 1);
        s1 += __shfl_xor_sync(0xffffffffu, s1, 2);
        l0 = l0 * al0 + s0;
        l1 = l1 * al1 + s1;

#pragma unroll
        for (int nt = 0; nt < 16; nt++) {
            O[nt][0] *= al0; O[nt][1] *= al0;
            O[nt][2] *= al1; O[nt][3] *= al1;
        }

        // ---- O += P @ V (B from row-major V via ldmatrix.trans) ----
        const unsigned vb = aVb + ((kt & 1) ? 17408u : 0u);
#pragma unroll
        for (int p = 0; p < 4; p++) {
            unsigned pa0 = pe[2 * p][0];
            unsigned pa1 = pe[2 * p][1];
            unsigned pa2 = pe[2 * p + 1][0];
            unsigned pa3 = pe[2 * p + 1][1];
#pragma unroll
            for (int nd2 = 0; nd2 < 8; nd2++) {
                unsigned b0, b1, b2, b3;
                ldsm4t(b0, b1, b2, b3, vb + p * 16 * P_ + nd2 * 32);
                mma_f16(O[2 * nd2],     pa0, pa1, pa2, pa3, b0, b1);
                mma_f16(O[2 * nd2 + 1], pa0, pa1, pa2, pa3, b2, b3);
            }
        }
    }

    // ---- normalize, store ctx row-major fp16 ----
    float inv0 = 1.0f / l0, inv1 = 1.0f / l1;
    size_t cb0 = ((size_t)(bb * S_ + gq0)) * NHH_ + hq * H_;
    size_t cb1 = ((size_t)(bb * S_ + gq1)) * NHH_ + hq * H_;
#pragma unroll
    for (int nt = 0; nt < 16; nt++) {
        int d = 8 * nt + 2 * tig;
        *(unsigned*)&g_ctxh[cb0 + d] = h2u(O[nt][0] * inv0, O[nt][1] * inv0);
        *(unsigned*)&g_ctxh[cb1 + d] = h2u(O[nt][2] * inv1, O[nt][3] * inv1);
    }
}

// =============================================================================
// Kernel 3: out = ctx @ Wo + enc, LayerNorm.  ldmatrix fragments, 4 k-chunks
// of 128, double-buffered A+W.  smem 104448 B: Ap @0/@17408, Ws @34816/@69632.
// Cs (64x132 floats) aliases Ap after the mainloop.
// =============================================================================
__global__ void __launch_bounds__(256, 2) out_kernel(
    const float* __restrict__ enc, const float* __restrict__ gamma,
    const float* __restrict__ beta, float* __restrict__ out)
{
    extern __shared__ char smc[];
    const unsigned sb = (unsigned)__cvta_generic_to_shared(smc);
    float* Cs = (float*)smc;
    const int tid = threadIdx.x, lane = tid & 31, wid = tid >> 5;
    const int gid = lane >> 2, tig = lane & 3;
    const int mw = wid & 1, nw = wid >> 1;
    const int m0 = blockIdx.x * 64;

    // prefetch chunk 0 (A + W)
#pragma unroll
    for (int t = 0; t < 4; t++) {
        int idx = tid + t * 256;
        int r = idx >> 4, q = idx & 15;
        cpa16(smc + r * P_ + 16 * q, g_ctxh + (size_t)(m0 + r) * NHH_ + 8 * q);
    }
#pragma unroll
    for (int t = 0; t < 8; t++) {
        int idx = tid + t * 256;
        int r = idx >> 4, q = idx & 15;
        cpa16(smc + 34816 + r * P_ + 16 * q, g_Woh + (size_t)r * 512 + 8 * q);
    }
    cp_commit();

    const unsigned aAl = (mw * 32 + (lane & 15)) * P_ + ((lane & 16) ? 16 : 0);
    const unsigned aBl = (nw * 32 + (lane & 7) + ((lane & 16) >> 1)) * P_ + ((lane & 8) ? 16 : 0);

    float c[2][4][4];
#pragma unroll
    for (int mt = 0; mt < 2; mt++)
#pragma unroll
        for (int nt = 0; nt < 4; nt++)
#pragma unroll
            for (int j = 0; j < 4; j++) c[mt][nt][j] = 0.0f;

    for (int kc = 0; kc < 4; kc++) {
        __syncthreads();
        if (kc < 3) {
            char* an = smc + (((kc + 1) & 1) ? 17408 : 0);
            char* wn = smc + 34816 + (((kc + 1) & 1) ? 34816 : 0);
#pragma unroll
            for (int t = 0; t < 4; t++) {
                int idx = tid + t * 256;
                int r = idx >> 4, q = idx & 15;
                cpa16(an + r * P_ + 16 * q,
                      g_ctxh + (size_t)(m0 + r) * NHH_ + (kc + 1) * 128 + 8 * q);
            }
#pragma unroll
            for (int t = 0; t < 8; t++) {
                int idx = tid + t * 256;
                int r = idx >> 4, q = idx & 15;
                cpa16(wn + r * P_ + 16 * q,
                      g_Woh + (size_t)r * 512 + (kc + 1) * 128 + 8 * q);
            }
            cp_commit();
            cp_wait<1>();
        } else {
            cp_wait<0>();
        }
        __syncthreads();

        const unsigned aA = sb + ((kc & 1) ? 17408u : 0u) + aAl;
        const unsigned aB = sb + 34816 + ((kc & 1) ? 34816u : 0u) + aBl;
#pragma unroll
        for (int ks = 0; ks < 8; ks++) {
            unsigned a00, a01, a02, a03, a10, a11, a12, a13;
            ldsm4(a00, a01, a02, a03, aA + ks * 32);
            ldsm4(a10, a11, a12, a13, aA + 16 * P_ + ks * 32);
#pragma unroll
            for (int nt2 = 0; nt2 < 2; nt2++) {
                unsigned b0, b1, b2, b3;
                ldsm4(b0, b1, b2, b3, aB + nt2 * 16 * P_ + ks * 32);
                mma_f16(c[0][2 * nt2],     a00, a01, a02, a03, b0, b1);
                mma_f16(c[0][2 * nt2 + 1], a00, a01, a02, a03, b2, b3);
                mma_f16(c[1][2 * nt2],     a10, a11, a12, a13, b0, b1);
                mma_f16(c[1][2 * nt2 + 1], a10, a11, a12, a13, b2, b3);
            }
        }
    }
    __syncthreads();                     // done with buffers -> reuse as Cs

#pragma unroll
    for (int mt = 0; mt < 2; mt++)
#pragma unroll
        for (int hf = 0; hf < 2; hf++) {
            int rr = mw * 32 + mt * 16 + hf * 8 + gid;
#pragma unroll
            for (int nt = 0; nt < 4; nt++) {
                int col = nw * 32 + nt * 8 + 2 * tig;
                *(float2*)&Cs[rr * 132 + col] =
                    make_float2(c[mt][nt][hf * 2 + 0], c[mt][nt][hf * 2 + 1]);
            }
        }
    __syncthreads();

    // ---- LayerNorm: 4 threads per row, 32 cols each ----
    const int row = tid >> 2, q = tid & 3;
    float x[32];
    float ssum = 0.0f, ssq = 0.0f;
#pragma unroll
    for (int i = 0; i < 8; i++) {
        float4 v = *(float4*)&Cs[row * 132 + q * 32 + i * 4];
        float4 e = *(const float4*)&enc[(size_t)(m0 + row) * H_ + q * 32 + i * 4];
        x[4 * i + 0] = v.x + e.x; x[4 * i + 1] = v.y + e.y;
        x[4 * i + 2] = v.z + e.z; x[4 * i + 3] = v.w + e.w;
#pragma unroll
        for (int j = 0; j < 4; j++) {
            ssum += x[4 * i + j];
            ssq  += x[4 * i + j] * x[4 * i + j];
        }
    }
    ssum += __shfl_xor_sync(0xffffffffu, ssum, 1);
    ssum += __shfl_xor_sync(0xffffffffu, ssum, 2);
    ssq  += __shfl_xor_sync(0xffffffffu, ssq,  1);
    ssq  += __shfl_xor_sync(0xffffffffu, ssq,  2);
    float mean = ssum * (1.0f / 128.0f);
    float var  = ssq * (1.0f / 128.0f) - mean * mean;
    float rstd = rsqrtf(var + 1e-6f);

#pragma unroll
    for (int i = 0; i < 8; i++) {
        float4 g  = *(const float4*)&gamma[q * 32 + i * 4];
        float4 be = *(const float4*)&beta[q * 32 + i * 4];
        float4 y = make_float4((x[4 * i + 0] - mean) * rstd * g.x + be.x,
                               (x[4 * i + 1] - mean) * rstd * g.y + be.y,
                               (x[4 * i + 2] - mean) * rstd * g.z + be.z,
                               (x[4 * i + 3] - mean) * rstd * g.w + be.w);
        *(float4*)&out[(size_t)(m0 + row) * H_ + q * 32 + i * 4] = y;
    }
}

// =============================================================================
extern "C" void kernel_launch(void* const* d_in, const int* in_sizes, int n_in,
                              void* d_out, int out_size)
{
    const float* enc   = (const float*)d_in[0];
    const int*   mask  = (const int*)  d_in[1];
    const float* Wq    = (const float*)d_in[2];
    const float* Wk    = (const float*)d_in[3];
    const float* Wv    = (const float*)d_in[4];
    const float* Wo    = (const float*)d_in[5];
    const float* gamma = (const float*)d_in[6];
    const float* beta  = (const float*)d_in[7];
    float* out = (float*)d_out;

    prep_kernel<<<1024, 256>>>(Wq, Wk, Wv, Wo);

    const int smem1 = 87040;
    cudaFuncSetAttribute(qkv_kernel, cudaFuncAttributeMaxDynamicSharedMemorySize, smem1);
    qkv_kernel<<<(B_ * S_) / 64, 256, smem1>>>(enc);

    const int smem2 = 104448;
    cudaFuncSetAttribute(attn_kernel, cudaFuncAttributeMaxDynamicSharedMemorySize, smem2);
    dim3 g2(S_ / 128, NH_, B_);
    attn_kernel<<<g2, 256, smem2>>>(mask);

    const int smem3 = 104448;
    cudaFuncSetAttribute(out_kernel, cudaFuncAttributeMaxDynamicSharedMemorySize, smem3);
    out_kernel<<<(B_ * S_) / 64, 256, smem3>>>(enc, gamma, beta, out);
}